// round 16
// baseline (speedup 1.0000x reference)
#include <cuda_runtime.h>
#include <cuda_fp16.h>
#include <cstdint>

// Problem constants (fixed by the reference)
#define T_DIM   8192
#define IN_DIM  4096
#define OUT_DIM 4096
#define RANK    32
#define GS      64
#define G_CNT   64
#define NCHUNK  65            // 64 main K-chunks + 1 lora chunk (32 lora + 32 zero)
#define TILE_M  128
#define TILE_N  128
#define MT_CNT  (T_DIM / TILE_M)    // 64
#define NT_CNT  (OUT_DIM / TILE_N)  // 32
#define A_CHUNK_H 8192        // 128 rows * 64 halves
#define B_CHUNK_H 8192        // 128 cols * 64 halves
#define A_CHUNK_BYTES 16384
#define B_CHUNK_BYTES 16384
#define STAGE_BYTES 32768
#define NSTAGE  3
#define DSMEM_BYTES (NSTAGE * STAGE_BYTES)   // 96 KB -> 2 CTAs/SM
#define KSPLIT  32
#define K3_KS   128           // k-span per k3 block

// Fused prep kernel block ranges (k2 first so only k1's tail drains)
#define PREP_B2   ((OUT_DIM * 512) / 256)          // 8192  k2_wdq blocks
#define PREP_B2B  ((IN_DIM * RANK) / 256)          // 512   k2_convert blocks
#define PREP_B1   ((T_DIM * G_CNT) / 8)            // 65536 k1 blocks
#define PREP_GRID (PREP_B2 + PREP_B2B + PREP_B1)

// ---------------------------------------------------------------------------
// Device-global scratch (allocation-free per harness rules)
// ---------------------------------------------------------------------------
__device__ __align__(128) __half g_Apk[(size_t)MT_CNT * NCHUNK * A_CHUNK_H];
__device__ __align__(128) __half g_Bpk[(size_t)NT_CNT * NCHUNK * B_CHUNK_H];
__device__ __align__(128) __half g_xsf16[(size_t)T_DIM * IN_DIM];   // smoothed acts (lora)
__device__ __align__(128) float  g_lapart[KSPLIT][(size_t)T_DIM * RANK];
__device__ __align__(128) __half g_pdT[(size_t)RANK * IN_DIM];      // proj_down^T fp16

// ---------------------------------------------------------------------------
// Helpers (sm_90-level features only: mbarrier + cp.async.bulk + mma.sync)
// ---------------------------------------------------------------------------
__device__ __forceinline__ uint32_t smem_to_u32(const void* p) {
    uint32_t a;
    asm("{ .reg .u64 t; cvta.to.shared.u64 t, %1; cvt.u32.u64 %0, t; }"
        : "=r"(a) : "l"(p));
    return a;
}

__device__ __forceinline__ uint32_t elect_one_pred() {
    uint32_t pred;
    asm volatile(
        "{\n\t.reg .pred p;\n\telect.sync _|p, 0xFFFFFFFF;\n\t"
        "selp.b32 %0, 1, 0, p;\n\t}"
        : "=r"(pred));
    return pred;
}

#define MBARRIER_INIT(mbar, count) \
    asm volatile("mbarrier.init.shared.b64 [%0], %1;" \
        :: "r"((uint32_t)(mbar)), "r"((uint32_t)(count)) : "memory")

#define MBARRIER_INVAL(mbar) \
    asm volatile("mbarrier.inval.shared.b64 [%0];" \
        :: "r"((uint32_t)(mbar)) : "memory")

#define MBARRIER_EXPECT_TX(mbar, bytes) \
    asm volatile("mbarrier.arrive.expect_tx.shared.b64 _, [%0], %1;" \
        :: "r"((uint32_t)(mbar)), "r"((uint32_t)(bytes)) : "memory")

#define MBARRIER_ARRIVE(mbar) \
    asm volatile("mbarrier.arrive.shared.b64 _, [%0];" \
        :: "r"((uint32_t)(mbar)) : "memory")

#define MBARRIER_WAIT_PARITY(mbar, parity) do { \
    uint32_t _mbar = (uint32_t)(mbar); \
    uint32_t _par  = (uint32_t)(parity); \
    uint32_t _done; \
    asm volatile( \
        "{\n\t.reg .pred p;\n\t" \
        "mbarrier.try_wait.parity.acquire.cta.shared::cta.b64 p, [%1], %2;\n\t" \
        "selp.b32 %0, 1, 0, p;\n\t}" \
        : "=r"(_done) : "r"(_mbar), "r"(_par) : "memory"); \
    if (!_done) { \
        asm volatile( \
            "{\n\t.reg .pred P1;\n\t" \
            "WAIT_LOOP_%=:\n\t" \
            "mbarrier.try_wait.parity.acquire.cta.shared::cta.b64 P1, [%0], %1, 0x989680;\n\t" \
            "@P1 bra.uni WAIT_DONE_%=;\n\t" \
            "bra.uni WAIT_LOOP_%=;\n\t" \
            "WAIT_DONE_%=:\n\t}" \
            :: "r"(_mbar), "r"(_par) : "memory"); \
    } \
} while (0)

#define FENCE_PROXY_ASYNC() \
    asm volatile("fence.proxy.async.shared::cta;" ::: "memory")

// 1-D bulk copy GMEM -> SMEM with mbarrier transaction completion (SASS: UBLKCP)
#define CP_ASYNC_BULK(dst_smem, src_gmem, bytes, mbar) \
    asm volatile( \
        "cp.async.bulk.shared::cluster.global.mbarrier::complete_tx::bytes " \
        "[%0], [%1], %2, [%3];" \
        :: "r"((uint32_t)(dst_smem)), "l"(src_gmem), "r"((uint32_t)(bytes)), \
           "r"((uint32_t)(mbar)) : "memory")

__device__ __forceinline__ void ldsm4(uint32_t addr, uint32_t f[4]) {
    asm volatile("ldmatrix.sync.aligned.m8n8.x4.shared.b16 {%0,%1,%2,%3}, [%4];"
                 : "=r"(f[0]), "=r"(f[1]), "=r"(f[2]), "=r"(f[3]) : "r"(addr));
}

// swizzled half-index within a 64-half (128B) row: 16B chunk XOR (row&7)
__device__ __forceinline__ int swz_h(int h, int r) {
    return (((h >> 3) ^ (r & 7)) << 3) | (h & 7);
}

// ---------------------------------------------------------------------------
// Fused prep kernel: k2_wdq blocks first, then k2_convert, then k1 (largest
// tail last). All three parts are independent memory streams.
// ---------------------------------------------------------------------------
__global__ void k_prep(const float* __restrict__ x, const float* __restrict__ smooth,
                       const int* __restrict__ qw, const float* __restrict__ wscales,
                       const float* __restrict__ pu, const float* __restrict__ pd) {
    int b = blockIdx.x;
    int tid = threadIdx.x;

    if (b < PREP_B2) {
        // ---- k2_wdq: wdq = qw * wscale[g][o] into packed+swizzled B ----
        int idx = b * 256 + tid;
        int o   = idx >> 9;
        int rem = idx & 511;
        int c   = rem >> 3;
        int c16 = rem & 7;
        float ws = __ldg(&wscales[(size_t)c * OUT_DIM + o]);

        int k = c * 64 + c16 * 8;
        const int4* qp = (const int4*)(qw + (size_t)o * IN_DIM + k);
        int4 v0 = qp[0], v1 = qp[1];
        __half2 p0 = __floats2half2_rn((float)v0.x * ws, (float)v0.y * ws);
        __half2 p1 = __floats2half2_rn((float)v0.z * ws, (float)v0.w * ws);
        __half2 p2 = __floats2half2_rn((float)v1.x * ws, (float)v1.y * ws);
        __half2 p3 = __floats2half2_rn((float)v1.z * ws, (float)v1.w * ws);
        uint4 w;
        w.x = *(uint32_t*)&p0; w.y = *(uint32_t*)&p1;
        w.z = *(uint32_t*)&p2; w.w = *(uint32_t*)&p3;

        int nt = o >> 7, col = o & 127;
        size_t base = ((size_t)(nt * NCHUNK + c) * 128 + col) * 64;
        int phys16 = c16 ^ (col & 7);
        *(uint4*)(g_Bpk + base + phys16 * 8) = w;
        return;
    }
    if (b < PREP_B2 + PREP_B2B) {
        // ---- k2_convert: proj_down^T fp16; B lora chunk ----
        int idx = (b - PREP_B2) * 256 + tid;
        int rr = idx >> 12;
        int k  = idx & 4095;
        g_pdT[(size_t)rr * IN_DIM + k] = __float2half(pd[(size_t)k * RANK + rr]);

        if (idx < OUT_DIM * 8) {
            int o = idx >> 3, c16 = idx & 7;
            uint4 w;
            if (c16 < 4) {
                const float* src = pu + (size_t)o * RANK + c16 * 8;
                __half2 p0 = __floats2half2_rn(src[0], src[1]);
                __half2 p1 = __floats2half2_rn(src[2], src[3]);
                __half2 p2 = __floats2half2_rn(src[4], src[5]);
                __half2 p3 = __floats2half2_rn(src[6], src[7]);
                w.x = *(uint32_t*)&p0; w.y = *(uint32_t*)&p1;
                w.z = *(uint32_t*)&p2; w.w = *(uint32_t*)&p3;
            } else {
                w = make_uint4(0, 0, 0, 0);
            }
            int nt = o >> 7, col = o & 127;
            size_t base = ((size_t)(nt * NCHUNK + 64) * 128 + col) * 64;
            int phys16 = c16 ^ (col & 7);
            *(uint4*)(g_Bpk + base + phys16 * 8) = w;
        }
        return;
    }

    // ---- k1: smooth + per-(token,group) int4 quantization ----
    int warp = (b - PREP_B2 - PREP_B2B) * 8 + (tid >> 5);
    int lane = tid & 31;
    int t = warp >> 6;
    int g = warp & 63;
    int base = g * GS;
    size_t xoff = (size_t)t * IN_DIM + base;

    float xs0 = __fdividef(x[xoff + lane],      smooth[base + lane]);
    float xs1 = __fdividef(x[xoff + lane + 32], smooth[base + lane + 32]);

    g_xsf16[xoff + lane]      = __float2half(xs0);
    g_xsf16[xoff + lane + 32] = __float2half(xs1);

    float m = fmaxf(fabsf(xs0), fabsf(xs1));
    #pragma unroll
    for (int o = 16; o > 0; o >>= 1)
        m = fmaxf(m, __shfl_xor_sync(0xffffffffu, m, o));

    float ascale = m / 7.0f;                 // matches reference amax/7.0
    if (ascale == 0.0f) ascale = 1.0f;       // matches jnp.where

    float q0 = fminf(fmaxf(rintf(xs0 / ascale), -8.0f), 7.0f);
    float q1 = fminf(fmaxf(rintf(xs1 / ascale), -8.0f), 7.0f);

    int mt = t >> 7, r = t & 127;
    size_t pkbase = ((size_t)(mt * NCHUNK + g) * 128 + r) * 64;
    g_Apk[pkbase + swz_h(lane, r)]      = __float2half(q0 * ascale);
    g_Apk[pkbase + swz_h(lane + 32, r)] = __float2half(q1 * ascale);
}

// ---------------------------------------------------------------------------
// K3: lora partials, split-K x32, pdT slice staged in smem.
// ---------------------------------------------------------------------------
#define PD_STRIDE 136   // halves (68 words)
__global__ void k3_lora() {
    __shared__ __align__(16) __half s_pd[RANK * PD_STRIDE];

    int tid  = threadIdx.x;
    int warp = tid >> 5;
    int lane = tid & 31;
    int gid  = lane >> 2;
    int tig  = lane & 3;
    int mblk   = blockIdx.x >> 5;    // 0..63
    int kslice = blockIdx.x & 31;    // 0..31
    int m0 = mblk * 128 + warp * 16;
    int k0 = kslice * K3_KS;

    // stage pd^T slice [32 rows x 128 halves] into smem (2x int4 per thread)
    {
        int r   = tid >> 3;          // 0..31
        int seg = (tid & 7) * 16;    // halves
        const int4* src = (const int4*)(g_pdT + (size_t)r * IN_DIM + k0 + seg);
        int4* dst = (int4*)(s_pd + r * PD_STRIDE + seg);
        dst[0] = src[0];
        dst[1] = src[1];
    }
    __syncthreads();

    float acc[4][4];
    #pragma unroll
    for (int ni = 0; ni < 4; ni++)
        #pragma unroll
        for (int j = 0; j < 4; j++) acc[ni][j] = 0.0f;

    const uint32_t* xsr0 = (const uint32_t*)(g_xsf16 + (size_t)(m0 + gid) * IN_DIM + k0);
    const uint32_t* xsr1 = (const uint32_t*)(g_xsf16 + (size_t)(m0 + gid + 8) * IN_DIM + k0);

    #pragma unroll
    for (int ks = 0; ks < K3_KS / 16; ks++) {
        int kb = ks * 8 + tig;
        uint32_t a0 = xsr0[kb];
        uint32_t a1 = xsr1[kb];
        uint32_t a2 = xsr0[kb + 4];
        uint32_t a3 = xsr1[kb + 4];
        #pragma unroll
        for (int ni = 0; ni < 4; ni++) {
            int c = ni * 8 + gid;
            const __half* bp = s_pd + c * PD_STRIDE + ks * 16;
            uint32_t b0 = *(const uint32_t*)(bp + tig * 2);
            uint32_t b1 = *(const uint32_t*)(bp + 8 + tig * 2);
            asm volatile(
                "mma.sync.aligned.m16n8k16.row.col.f32.f16.f16.f32 "
                "{%0,%1,%2,%3},{%4,%5,%6,%7},{%8,%9},{%0,%1,%2,%3};"
                : "+f"(acc[ni][0]), "+f"(acc[ni][1]), "+f"(acc[ni][2]), "+f"(acc[ni][3])
                : "r"(a0), "r"(a1), "r"(a2), "r"(a3), "r"(b0), "r"(b1));
        }
    }

    float* dst = g_lapart[kslice];
    #pragma unroll
    for (int ni = 0; ni < 4; ni++) {
        int col = ni * 8 + tig * 2;
        *(float2*)(dst + (size_t)(m0 + gid) * RANK + col)     = make_float2(acc[ni][0], acc[ni][1]);
        *(float2*)(dst + (size_t)(m0 + gid + 8) * RANK + col) = make_float2(acc[ni][2], acc[ni][3]);
    }
}

// K3b: reduce partials -> A lora chunk (fp16) + zero pad
__global__ void k3b_reduce() {
    int idx = blockIdx.x * blockDim.x + threadIdx.x;   // over T*RANK
    float s = 0.0f;
    #pragma unroll
    for (int i = 0; i < KSPLIT; i++) s += g_lapart[i][idx];
    int t = idx >> 5, rk = idx & 31;
    int mt = t >> 7, r = t & 127;
    size_t base = ((size_t)(mt * NCHUNK + 64) * 128 + r) * 64;
    g_Apk[base + swz_h(rk, r)]      = __float2half(s);
    g_Apk[base + swz_h(rk + 32, r)] = __float2half(0.0f);
}

// ---------------------------------------------------------------------------
// K4: fp16 HMMA GEMM, tile 128x128, 65 K-chunks, 2 CTAs/SM, 3-stage
// cp.async.bulk pipeline with full (tx) + empty (count=8) mbarrier ring.
// Empty-arrive fires right after the last fragment-load batch of a chunk
// (fragments are register-resident; per-warp in-order issue guarantees the
// smem reads precede the arrive), releasing each stage ~one mma-batch early.
// ---------------------------------------------------------------------------
__global__ void __launch_bounds__(256, 2)
k4_main(float* __restrict__ out) {
    extern __shared__ __align__(128) char dsm[];
    __shared__ __align__(8) unsigned long long s_full[NSTAGE];
    __shared__ __align__(8) unsigned long long s_empty[NSTAGE];

    int tid  = threadIdx.x;
    int wid  = tid >> 5;
    int lane = tid & 31;
    int gid  = lane >> 2;
    int tig  = lane & 3;
    int wm   = (wid >> 2) * 64;     // warp row offset: 0 or 64
    int wn   = (wid & 3) * 32;      // warp col offset: 0,32,64,96

    uint32_t smem = smem_to_u32(dsm);
    uint32_t mbF[NSTAGE], mbE[NSTAGE];
    #pragma unroll
    for (int s = 0; s < NSTAGE; s++) {
        mbF[s] = smem_to_u32(&s_full[s]);
        mbE[s] = smem_to_u32(&s_empty[s]);
    }

    // L2-friendly swizzle: 16-mt chunks sweep all 32 nt (~50MB working set)
    int bid = blockIdx.x;                     // 0..2047
    int mt  = ((bid >> 9) << 4) + (bid & 15); // 0..63
    int nt  = (bid >> 4) & 31;                // 0..31
    int m0 = mt * TILE_M, n0 = nt * TILE_N;

    const __half* gA = g_Apk + (size_t)mt * NCHUNK * A_CHUNK_H;
    const __half* gB = g_Bpk + (size_t)nt * NCHUNK * B_CHUNK_H;

    if (tid == 0) {
        #pragma unroll
        for (int s = 0; s < NSTAGE; s++) {
            MBARRIER_INIT(mbF[s], 1);
            MBARRIER_INIT(mbE[s], 8);
        }
    }
    __syncthreads();

    bool leader = elect_one_pred() != 0;

    // prologue: fill all 3 stages (chunks 0..2)
    if (wid == 0 && leader) {
        #pragma unroll
        for (int s = 0; s < NSTAGE; s++) {
            uint32_t sA = smem + s * STAGE_BYTES;
            MBARRIER_EXPECT_TX(mbF[s], STAGE_BYTES);
            CP_ASYNC_BULK(sA,                 gA + (size_t)s * A_CHUNK_H, A_CHUNK_BYTES, mbF[s]);
            CP_ASYNC_BULK(sA + A_CHUNK_BYTES, gB + (size_t)s * B_CHUNK_H, B_CHUNK_BYTES, mbF[s]);
        }
    }

    // ldmatrix lane-dependent address parts (proven round-8/10/12 mapping)
    int rA_off = ((lane >> 3) & 1) * 8 + (lane & 7);
    int cA_off = lane >> 4;           // 0/1
    int rB_off = (lane >> 4) * 8 + (lane & 7);
    int cB_off = (lane >> 3) & 1;     // 0/1

    uint32_t aRow[4], aXor[4], bRow[2], bXor[2];
    #pragma unroll
    for (int mi = 0; mi < 4; mi++) {
        int r = wm + mi * 16 + rA_off;
        aRow[mi] = (uint32_t)(r * 128);
        aXor[mi] = (uint32_t)((r & 7) << 4);
    }
    #pragma unroll
    for (int nb = 0; nb < 2; nb++) {
        int c = wn + nb * 16 + rB_off;
        bRow[nb] = (uint32_t)(c * 128);
        bXor[nb] = (uint32_t)((c & 7) << 4);
    }

    float acc[4][4][4];
    #pragma unroll
    for (int a = 0; a < 4; a++)
        #pragma unroll
        for (int b = 0; b < 4; b++)
            #pragma unroll
            for (int c = 0; c < 4; c++) acc[a][b][c] = 0.0f;

    int st = 0, ph = 0;
    #pragma unroll 1
    for (int g = 0; g < NCHUNK; g++) {
        uint32_t sA = smem + st * STAGE_BYTES;
        uint32_t sB = sA + A_CHUNK_BYTES;

        MBARRIER_WAIT_PARITY(mbF[st], ph);

        #pragma unroll
        for (int ks = 0; ks < 4; ks++) {
            uint32_t cA16 = (uint32_t)((2 * ks + cA_off) << 4);
            uint32_t cB16 = (uint32_t)((2 * ks + cB_off) << 4);

            uint32_t bfr[2][4];
            #pragma unroll
            for (int nb = 0; nb < 2; nb++)
                ldsm4(sB + bRow[nb] + (cB16 ^ bXor[nb]), bfr[nb]);

            uint32_t afr[4][4];
            #pragma unroll
            for (int mi = 0; mi < 4; mi++)
                ldsm4(sA + aRow[mi] + (cA16 ^ aXor[mi]), afr[mi]);

            // last fragment batch of this chunk issued -> stage is reusable
            if (ks == 3 && leader) MBARRIER_ARRIVE(mbE[st]);

            #pragma unroll
            for (int mi = 0; mi < 4; mi++) {
                #pragma unroll
                for (int nb = 0; nb < 2; nb++) {
                    #pragma unroll
                    for (int q = 0; q < 2; q++) {
                        int ni = nb * 2 + q;
                        asm volatile(
                            "mma.sync.aligned.m16n8k16.row.col.f32.f16.f16.f32 "
                            "{%0,%1,%2,%3},{%4,%5,%6,%7},{%8,%9},{%0,%1,%2,%3};"
                            : "+f"(acc[mi][ni][0]), "+f"(acc[mi][ni][1]),
                              "+f"(acc[mi][ni][2]), "+f"(acc[mi][ni][3])
                            : "r"(afr[mi][0]), "r"(afr[mi][1]),
                              "r"(afr[mi][2]), "r"(afr[mi][3]),
                              "r"(bfr[nb][2 * q]), "r"(bfr[nb][2 * q + 1]));
                    }
                }
            }
        }

        // producer: refill once all 8 warps have released this stage
        int gp = g + NSTAGE;
        if (gp < NCHUNK && wid == 0 && leader) {
            MBARRIER_WAIT_PARITY(mbE[st], ph);
            FENCE_PROXY_ASYNC();
            MBARRIER_EXPECT_TX(mbF[st], STAGE_BYTES);
            CP_ASYNC_BULK(sA, gA + (size_t)gp * A_CHUNK_H, A_CHUNK_BYTES, mbF[st]);
            CP_ASYNC_BULK(sB, gB + (size_t)gp * B_CHUNK_H, B_CHUNK_BYTES, mbF[st]);
        }

        if (++st == NSTAGE) { st = 0; ph ^= 1; }
    }

    // ---------------- store ----------------
    #pragma unroll
    for (int mi = 0; mi < 4; mi++) {
        int r0 = m0 + wm + mi * 16 + gid;
        #pragma unroll
        for (int nb = 0; nb < 2; nb++) {
            #pragma unroll
            for (int q = 0; q < 2; q++) {
                int ni = nb * 2 + q;
                int c = n0 + wn + nb * 16 + q * 8 + tig * 2;
                *(float2*)(out + (size_t)r0 * OUT_DIM + c) =
                    make_float2(acc[mi][ni][0], acc[mi][ni][1]);
                *(float2*)(out + (size_t)(r0 + 8) * OUT_DIM + c) =
                    make_float2(acc[mi][ni][2], acc[mi][ni][3]);
            }
        }
    }

    __syncthreads();
    if (tid == 0) {
        #pragma unroll
        for (int s = 0; s < NSTAGE; s++) {
            MBARRIER_INVAL(mbF[s]);
            MBARRIER_INVAL(mbE[s]);
        }
    }
}

// ---------------------------------------------------------------------------
// kernel_launch — serial single-stream topology (round-14 proven)
// inputs: x[f32], qweight[i32], wscales[f32], smooth_factor[f32],
//         proj_down[f32], proj_up[f32]; output: f32 [T, OUT]
// ---------------------------------------------------------------------------
extern "C" void kernel_launch(void* const* d_in, const int* in_sizes, int n_in,
                              void* d_out, int out_size) {
    (void)in_sizes; (void)n_in; (void)out_size;
    const float* x         = (const float*)d_in[0];
    const int*   qweight   = (const int*)d_in[1];
    const float* wscales   = (const float*)d_in[2];
    const float* smooth    = (const float*)d_in[3];
    const float* proj_down = (const float*)d_in[4];
    const float* proj_up   = (const float*)d_in[5];
    float* out = (float*)d_out;

    cudaFuncSetAttribute(k4_main, cudaFuncAttributeMaxDynamicSharedMemorySize,
                         DSMEM_BYTES);

    k_prep<<<PREP_GRID, 256>>>(x, smooth, qweight, wscales, proj_up, proj_down);
    k3_lora<<<MT_CNT * KSPLIT, 256>>>();
    k3b_reduce<<<(T_DIM * RANK) / 256, 256>>>();
    k4_main<<<MT_CNT * NT_CNT, 256, DSMEM_BYTES>>>(out);
}